// round 13
// baseline (speedup 1.0000x reference)
#include <cuda_runtime.h>
#include <cstdint>

#define BB 16
#define NN 1024
#define DD 64
#define NHH 4
#define HDD 16
#define HH 256
#define WW 256

#define NCHUNK 4
#define BPC (BB/NCHUNK)          // 4 batches per chunk

// ---------------- scratch (device globals: no runtime allocation) ----------
__device__ float g_Q[BB*NHH*NN*HDD];          // (b,h,n,j) 4MB
__device__ float g_K[BB*NHH*NN*HDD];          // 4MB
__device__ float g_V[BB*NHH*NN*HDD];          // 4MB
__device__ float g_PF[BB*NN*DD];              // patch means 4MB
__device__ float g_att[BB*NN*DD];             // pose-scaled attention out 4MB
__device__ float g_pose[BB*DD];               // 1 + pose_mod

// ---------------- helpers ---------------------------------------------------
__device__ __forceinline__ float ex2f(float x) {
    float y;
    asm("ex2.approx.f32 %0, %1;" : "=f"(y) : "f"(x));
    return y;
}
__device__ __forceinline__ uint32_t tf32cvt(float f) {
    uint32_t u;
    asm("cvt.rna.tf32.f32 %0, %1;" : "=r"(u) : "f"(f));
    return u;
}
__device__ __forceinline__ void mma_tf32(float& d0, float& d1, float& d2, float& d3,
                                         uint32_t a0, uint32_t a1, uint32_t a2, uint32_t a3,
                                         uint32_t b0, uint32_t b1) {
    asm("mma.sync.aligned.m16n8k8.row.col.f32.tf32.tf32.f32 "
        "{%0,%1,%2,%3}, {%4,%5,%6,%7}, {%8,%9}, {%0,%1,%2,%3};"
        : "+f"(d0), "+f"(d1), "+f"(d2), "+f"(d3)
        : "r"(a0), "r"(a1), "r"(a2), "r"(a3), "r"(b0), "r"(b1));
}

// ---------------- K1: patch-mean gather chunk (paired-lane coalesced) -------
// Blocks [0,256): 16 points/block within the chunk's 4 batches.
// Blocks [256,260): pose tail for the chunk's batches.
__global__ __launch_bounds__(256) void gather_kernel(
    const float* __restrict__ feat, const int* __restrict__ coords,
    const float* __restrict__ pe, const float* __restrict__ Wp,
    const float* __restrict__ bp, int chunk)
{
    if (blockIdx.x >= 256) {            // ---- pose tail blocks ----
        int b = chunk*BPC + (blockIdx.x - 256);
        int d = threadIdx.x;
        if (d < 64) {
            float s = bp[d];
            #pragma unroll 8
            for (int p = 0; p < 64; p++) s += pe[b*64 + p] * Wp[p*64 + d];
            g_pose[b*64 + d] = 1.0f + s;
        }
        return;
    }

    int t = threadIdx.x, w = t >> 5, lane = t & 31;
    int ch2 = lane >> 1, half = lane & 1;
    int gb = chunk*256 + blockIdx.x;

    #pragma unroll
    for (int ip = 0; ip < 2; ip++) {
        int gp = gb*16 + w*2 + ip;
        int b  = gp >> 10;
        int y = __ldg(coords + gp*2 + 0);    // warp-uniform
        int x = __ldg(coords + gp*2 + 1);
        int s = x - 2;
        bool fast = (s >= 0) && (s <= 248);

        float part[4] = {0.f, 0.f, 0.f, 0.f};

        if (fast) {
            int a = s & ~3;
            int o = s - a;
            #pragma unroll
            for (int dy = 0; dy < 5; dy++) {
                int yy = y + dy - 2;
                int yc = min(max(yy, 0), HH-1);
                float m = (yy == yc) ? 1.0f : 0.0f;
                #pragma unroll
                for (int cp = 0; cp < 4; cp++) {
                    int ch = cp*16 + ch2;
                    const float4* p = (const float4*)
                        (feat + ((size_t)(b*64 + ch) << 16) + yc*WW + a) + half;
                    float4 v = __ldg(p);
                    float ps;
                    if (half == 0) {
                        ps = v.w;
                        if (o < 3) ps += v.z;
                        if (o < 2) ps += v.y;
                        if (o < 1) ps += v.x;
                    } else {
                        ps = v.x;
                        if (o > 0) ps += v.y;
                        if (o > 1) ps += v.z;
                        if (o > 2) ps += v.w;
                    }
                    part[cp] = fmaf(m, ps, part[cp]);
                }
            }
        } else {
            int base = x - 2 + half*4;
            int cnt  = half ? 1 : 4;
            for (int dy = 0; dy < 5; dy++) {
                int yy = y + dy - 2;
                if (yy < 0 || yy >= HH) continue;
                #pragma unroll
                for (int cp = 0; cp < 4; cp++) {
                    int ch = cp*16 + ch2;
                    const float* row = feat + ((size_t)(b*64 + ch) << 16) + yy*WW;
                    float ps = 0.f;
                    #pragma unroll
                    for (int i = 0; i < 4; i++) {
                        if (i < cnt) {
                            int xx = base + i;
                            if (xx >= 0 && xx < WW) ps += __ldg(row + xx);
                        }
                    }
                    part[cp] += ps;
                }
            }
        }

        #pragma unroll
        for (int cp = 0; cp < 4; cp++) {
            float tot = part[cp] + __shfl_xor_sync(0xffffffff, part[cp], 1);
            if (half == 0)
                g_PF[(size_t)gp*64 + cp*16 + ch2] = tot * 0.04f;
        }
    }
}

// ---------------- K2: Q/K/V projection via tf32 mma (chunked) ---------------
#define ASTR 68
#define BSTR 136
extern __shared__ uint32_t PS[];
__global__ __launch_bounds__(256) void projection_mma_kernel(
    const float* __restrict__ desc,
    const float* __restrict__ Wq, const float* __restrict__ bq,
    const float* __restrict__ Wk, const float* __restrict__ bk,
    const float* __restrict__ Wv, const float* __restrict__ bv, int chunk)
{
    uint32_t* As = PS;                  // 128 x ASTR
    uint32_t* Bs = PS + 128*ASTR;       // 64 x BSTR

    int t = threadIdx.x;
    int w = t >> 5, lane = t & 31, g = lane >> 2, t4 = lane & 3;
    int gp0 = chunk*BPC*NN + blockIdx.x * 128;
    int b = gp0 >> 10, n0 = gp0 & 1023;

    // ======== pass 1: Q ========
    #pragma unroll
    for (int it = 0; it < 8; it++) {
        int i = t + 256*it;
        int r = i >> 4, c4 = (i & 15)*4;
        float4 v = __ldg((const float4*)(desc + (size_t)(gp0 + r)*64 + c4));
        *(uint4*)&As[r*ASTR + c4] =
            make_uint4(tf32cvt(v.x), tf32cvt(v.y), tf32cvt(v.z), tf32cvt(v.w));
    }
    #pragma unroll
    for (int it = 0; it < 4; it++) {
        int i = t + 256*it;
        int k = i >> 4, n4 = (i & 15)*4;
        float4 v = __ldg((const float4*)(Wq + k*64 + n4));
        *(uint4*)&Bs[k*BSTR + n4] =
            make_uint4(tf32cvt(v.x), tf32cvt(v.y), tf32cvt(v.z), tf32cvt(v.w));
    }
    __syncthreads();

    {
        uint32_t a[8][4];
        #pragma unroll
        for (int kc = 0; kc < 8; kc++) {
            int r0 = (w*16 + g)*ASTR + kc*8 + t4;
            a[kc][0] = As[r0];           a[kc][1] = As[r0 + 8*ASTR];
            a[kc][2] = As[r0 + 4];       a[kc][3] = As[r0 + 8*ASTR + 4];
        }
        #pragma unroll
        for (int nch = 0; nch < 8; nch++) {
            float d0=0.f, d1=0.f, d2=0.f, d3=0.f;
            #pragma unroll
            for (int kc = 0; kc < 8; kc++)
                mma_tf32(d0,d1,d2,d3, a[kc][0],a[kc][1],a[kc][2],a[kc][3],
                         Bs[(kc*8 + t4)*BSTR + nch*8 + g],
                         Bs[(kc*8 + t4 + 4)*BSTR + nch*8 + g]);
            int c = nch*8 + 2*t4;
            float bb0 = __ldg(bq + c), bb1 = __ldg(bq + c + 1);
            int h = c >> 4, j = c & 15;
            size_t idx = ((size_t)(b*NHH + h)*NN + n0 + w*16 + g)*HDD + j;
            *(float2*)&g_Q[idx]          = make_float2(d0 + bb0, d1 + bb1);
            *(float2*)&g_Q[idx + 8*HDD]  = make_float2(d2 + bb0, d3 + bb1);
        }
    }
    __syncthreads();

    // ======== pass 2: K | V ========
    #pragma unroll
    for (int it = 0; it < 8; it++) {
        int i = t + 256*it;
        int r = i >> 4, c4 = (i & 15)*4;
        float4 v = *(const float4*)(g_PF + (size_t)(gp0 + r)*64 + c4);
        *(uint4*)&As[r*ASTR + c4] =
            make_uint4(tf32cvt(v.x), tf32cvt(v.y), tf32cvt(v.z), tf32cvt(v.w));
    }
    #pragma unroll
    for (int it = 0; it < 4; it++) {
        int i = t + 256*it;
        int k = i >> 4, n4 = (i & 15)*4;
        float4 v = __ldg((const float4*)(Wk + k*64 + n4));
        *(uint4*)&Bs[k*BSTR + n4] =
            make_uint4(tf32cvt(v.x), tf32cvt(v.y), tf32cvt(v.z), tf32cvt(v.w));
    }
    #pragma unroll
    for (int it = 0; it < 4; it++) {
        int i = t + 256*it;
        int k = i >> 4, n4 = (i & 15)*4;
        float4 v = __ldg((const float4*)(Wv + k*64 + n4));
        *(uint4*)&Bs[k*BSTR + 64 + n4] =
            make_uint4(tf32cvt(v.x), tf32cvt(v.y), tf32cvt(v.z), tf32cvt(v.w));
    }
    __syncthreads();

    {
        uint32_t a[8][4];
        #pragma unroll
        for (int kc = 0; kc < 8; kc++) {
            int r0 = (w*16 + g)*ASTR + kc*8 + t4;
            a[kc][0] = As[r0];           a[kc][1] = As[r0 + 8*ASTR];
            a[kc][2] = As[r0 + 4];       a[kc][3] = As[r0 + 8*ASTR + 4];
        }
        #pragma unroll
        for (int nch = 0; nch < 16; nch++) {
            float d0=0.f, d1=0.f, d2=0.f, d3=0.f;
            #pragma unroll
            for (int kc = 0; kc < 8; kc++)
                mma_tf32(d0,d1,d2,d3, a[kc][0],a[kc][1],a[kc][2],a[kc][3],
                         Bs[(kc*8 + t4)*BSTR + nch*8 + g],
                         Bs[(kc*8 + t4 + 4)*BSTR + nch*8 + g]);
            int cfull = nch*8 + 2*t4;
            bool isK = (cfull < 64);
            int c = isK ? cfull : (cfull - 64);
            const float* bias = isK ? bk : bv;
            float* dst = isK ? g_K : g_V;
            float bb0 = __ldg(bias + c), bb1 = __ldg(bias + c + 1);
            int h = c >> 4, j = c & 15;
            size_t idx = ((size_t)(b*NHH + h)*NN + n0 + w*16 + g)*HDD + j;
            *(float2*)&dst[idx]         = make_float2(d0 + bb0, d1 + bb1);
            *(float2*)&dst[idx + 8*HDD] = make_float2(d2 + bb0, d3 + bb1);
        }
    }
}

// ---------------- K3: all-tf32 tensor-core attention (chunked) --------------
#define KPAD 20
#define VPAD 24
__global__ __launch_bounds__(256) void attn_mma_kernel(int chunk) {
    __shared__ uint32_t Ks[64*KPAD];
    __shared__ uint32_t Vs[64*VPAD];

    int t = threadIdx.x;
    int w = t >> 5, lane = t & 31, g = lane >> 2, t4 = lane & 3;
    int b = chunk*BPC + blockIdx.z, h = blockIdx.y;
    size_t bh = (size_t)(b*NHH + h) * NN * HDD;
    const float* Kg = g_K + bh;
    const float* Vg = g_V + bh;

    int qrow = blockIdx.x*128 + w*16;
    const float* Qp = g_Q + bh + (size_t)qrow*HDD;
    const float CSC = 0.25f * 1.4426950408889634f;

    uint32_t qa[2][4];
    #pragma unroll
    for (int c = 0; c < 2; c++) {
        qa[c][0] = tf32cvt(Qp[ g   *16 + c*8 + t4    ] * CSC);
        qa[c][1] = tf32cvt(Qp[(g+8)*16 + c*8 + t4    ] * CSC);
        qa[c][2] = tf32cvt(Qp[ g   *16 + c*8 + t4 + 4] * CSC);
        qa[c][3] = tf32cvt(Qp[(g+8)*16 + c*8 + t4 + 4] * CSC);
    }

    float o0[4] = {0,0,0,0};
    float o1[4] = {0,0,0,0};
    float rs0 = 0.0f, rs1 = 0.0f;

    int key = t >> 2, dc = t & 3;
    int vrow = (key & ~7) + 4*(key & 1) + ((key & 7) >> 1);

    float4 kreg = ((const float4*)Kg)[t];
    float4 vreg = ((const float4*)Vg)[t];

    for (int tile = 0; tile < 16; tile++) {
        __syncthreads();
        {
            uint32_t* kd = Ks + key*KPAD + dc*4;
            kd[0] = tf32cvt(kreg.x); kd[1] = tf32cvt(kreg.y);
            kd[2] = tf32cvt(kreg.z); kd[3] = tf32cvt(kreg.w);
            uint4 vv;
            vv.x = tf32cvt(vreg.x); vv.y = tf32cvt(vreg.y);
            vv.z = tf32cvt(vreg.z); vv.w = tf32cvt(vreg.w);
            *(uint4*)(Vs + vrow*VPAD + dc*4) = vv;
        }
        __syncthreads();
        if (tile < 15) {
            kreg = ((const float4*)(Kg + (size_t)(tile+1)*64*16))[t];
            vreg = ((const float4*)(Vg + (size_t)(tile+1)*64*16))[t];
        }

        #pragma unroll
        for (int j = 0; j < 8; j++) {
            float d0=0.f, d1=0.f, d2=0.f, d3=0.f;
            #pragma unroll
            for (int c = 0; c < 2; c++) {
                const uint32_t* kb = Ks + (j*8+g)*KPAD + c*8 + t4;
                mma_tf32(d0,d1,d2,d3, qa[c][0],qa[c][1],qa[c][2],qa[c][3],
                         kb[0], kb[4]);
            }
            float p0 = ex2f(d0), p1 = ex2f(d1), p2 = ex2f(d2), p3 = ex2f(d3);
            rs0 += p0 + p1;
            rs1 += p2 + p3;
            uint32_t a0 = __float_as_uint(p0), a1 = __float_as_uint(p2);
            uint32_t a2 = __float_as_uint(p1), a3 = __float_as_uint(p3);
            uint32_t b00 = Vs[(j*8 + t4    )*VPAD + g    ];
            uint32_t b01 = Vs[(j*8 + t4 + 4)*VPAD + g    ];
            uint32_t b10 = Vs[(j*8 + t4    )*VPAD + g + 8];
            uint32_t b11 = Vs[(j*8 + t4 + 4)*VPAD + g + 8];
            mma_tf32(o0[0],o0[1],o0[2],o0[3], a0,a1,a2,a3, b00,b01);
            mma_tf32(o1[0],o1[1],o1[2],o1[3], a0,a1,a2,a3, b10,b11);
        }
    }

    rs0 += __shfl_xor_sync(0xffffffff, rs0, 1);
    rs0 += __shfl_xor_sync(0xffffffff, rs0, 2);
    rs1 += __shfl_xor_sync(0xffffffff, rs1, 1);
    rs1 += __shfl_xor_sync(0xffffffff, rs1, 2);
    float inv0 = 1.0f / rs0;
    float inv1 = 1.0f / rs1;

    const float* ps = g_pose + b*64 + h*16;
    size_t r0 = ((size_t)b*NN + qrow + g    )*64 + h*16;
    size_t r1 = ((size_t)b*NN + qrow + g + 8)*64 + h*16;
    #pragma unroll
    for (int nd = 0; nd < 2; nd++) {
        const float* o = nd ? o1 : o0;
        int cc = nd*8 + 2*t4;
        float p0 = ps[cc], p1 = ps[cc+1];
        *(float2*)&g_att[r0 + cc] = make_float2(o[0]*inv0*p0, o[1]*inv0*p1);
        *(float2*)&g_att[r1 + cc] = make_float2(o[2]*inv1*p0, o[3]*inv1*p1);
    }
}

// ---------------- K4: out = g_att @ Wo + bo via tf32 mma (chunked) ----------
#define OBSTR 72
extern __shared__ uint32_t OS[];
__global__ __launch_bounds__(256) void outproj_mma_kernel(
    const float* __restrict__ Wo, const float* __restrict__ bo,
    float* __restrict__ out, int chunk)
{
    uint32_t* As = OS;
    uint32_t* Bs = OS + 128*ASTR;

    int t = threadIdx.x;
    int w = t >> 5, lane = t & 31, g = lane >> 2, t4 = lane & 3;
    size_t gp0 = (size_t)(chunk*32 + blockIdx.x) * 128;

    #pragma unroll
    for (int it = 0; it < 8; it++) {
        int i = t + 256*it;
        int r = i >> 4, c4 = (i & 15)*4;
        float4 v = *(const float4*)(g_att + (gp0 + r)*64 + c4);
        *(uint4*)&As[r*ASTR + c4] =
            make_uint4(tf32cvt(v.x), tf32cvt(v.y), tf32cvt(v.z), tf32cvt(v.w));
    }
    #pragma unroll
    for (int it = 0; it < 4; it++) {
        int i = t + 256*it;
        int k = i >> 4, n4 = (i & 15)*4;
        float4 v = __ldg((const float4*)(Wo + k*64 + n4));
        *(uint4*)&Bs[k*OBSTR + n4] =
            make_uint4(tf32cvt(v.x), tf32cvt(v.y), tf32cvt(v.z), tf32cvt(v.w));
    }
    __syncthreads();

    uint32_t a[8][4];
    #pragma unroll
    for (int kc = 0; kc < 8; kc++) {
        int r0 = (w*16 + g)*ASTR + kc*8 + t4;
        a[kc][0] = As[r0];           a[kc][1] = As[r0 + 8*ASTR];
        a[kc][2] = As[r0 + 4];       a[kc][3] = As[r0 + 8*ASTR + 4];
    }
    #pragma unroll
    for (int nch = 0; nch < 8; nch++) {
        float d0=0.f, d1=0.f, d2=0.f, d3=0.f;
        #pragma unroll
        for (int kc = 0; kc < 8; kc++)
            mma_tf32(d0,d1,d2,d3, a[kc][0],a[kc][1],a[kc][2],a[kc][3],
                     Bs[(kc*8 + t4)*OBSTR + nch*8 + g],
                     Bs[(kc*8 + t4 + 4)*OBSTR + nch*8 + g]);
        int c = nch*8 + 2*t4;
        float bb0 = __ldg(bo + c), bb1 = __ldg(bo + c + 1);
        size_t r0i = (gp0 + w*16 + g)*64 + c;
        *(float2*)&out[r0i]          = make_float2(d0 + bb0, d1 + bb1);
        *(float2*)&out[r0i + 8*64]   = make_float2(d2 + bb0, d3 + bb1);
    }
}

// ---------------- launch: dual-stream chunk pipeline -------------------------
extern "C" void kernel_launch(void* const* d_in, const int* in_sizes, int n_in,
                              void* d_out, int out_size) {
    const float* desc   = (const float*)d_in[0];
    const float* feat   = (const float*)d_in[1];
    const int*   coords = (const int*)  d_in[2];
    const float* pose   = (const float*)d_in[3];
    const float* Wq = (const float*)d_in[4];  const float* bq = (const float*)d_in[5];
    const float* Wk = (const float*)d_in[6];  const float* bk = (const float*)d_in[7];
    const float* Wv = (const float*)d_in[8];  const float* bv = (const float*)d_in[9];
    const float* Wp = (const float*)d_in[10]; const float* bp = (const float*)d_in[11];
    const float* Wo = (const float*)d_in[12]; const float* bo = (const float*)d_in[13];
    float* out = (float*)d_out;

    int psm = (128*ASTR + 64*BSTR) * 4;     // 69,632 B
    cudaFuncSetAttribute(projection_mma_kernel,
                         cudaFuncAttributeMaxDynamicSharedMemorySize, psm);
    int osm = (128*ASTR + 64*OBSTR) * 4;    // 53,248 B
    cudaFuncSetAttribute(outproj_mma_kernel,
                         cudaFuncAttributeMaxDynamicSharedMemorySize, osm);

    cudaStream_t s2;
    cudaStreamCreateWithFlags(&s2, cudaStreamNonBlocking);
    cudaEvent_t evG[NCHUNK], evDone;
    for (int c = 0; c < NCHUNK; c++)
        cudaEventCreateWithFlags(&evG[c], cudaEventDisableTiming);
    cudaEventCreateWithFlags(&evDone, cudaEventDisableTiming);

    // main stream: gather chunks back-to-back (DRAM-bound)
    for (int c = 0; c < NCHUNK; c++) {
        gather_kernel<<<256 + BPC, 256>>>(feat, coords, pose, Wp, bp, c);
        cudaEventRecord(evG[c], 0);
    }
    // side stream: compute chain per chunk (tensor/MUFU-bound), overlapped
    for (int c = 0; c < NCHUNK; c++) {
        cudaStreamWaitEvent(s2, evG[c], 0);
        projection_mma_kernel<<<32, 256, psm, s2>>>(desc, Wq, bq, Wk, bk, Wv, bv, c);
        attn_mma_kernel<<<dim3(8, NHH, BPC), 256, 0, s2>>>(c);
        outproj_mma_kernel<<<32, 256, osm, s2>>>(Wo, bo, out, c);
    }
    cudaEventRecord(evDone, s2);
    cudaStreamWaitEvent(0, evDone, 0);
}

// round 14
// speedup vs baseline: 1.9588x; 1.9588x over previous
#include <cuda_runtime.h>
#include <cstdint>

#define BB 16
#define NN 1024
#define DD 64
#define NHH 4
#define HDD 16
#define HH 256
#define WW 256

// ---------------- scratch (device globals: no runtime allocation) ----------
__device__ float g_Q[BB*NHH*NN*HDD];          // (b,h,n,j) 4MB
__device__ float g_K[BB*NHH*NN*HDD];          // 4MB
__device__ float g_V[BB*NHH*NN*HDD];          // 4MB
__device__ float g_PF[BB*NN*DD];              // patch means 4MB
__device__ float g_att[BB*NN*DD];             // pose-scaled attention out 4MB
__device__ float g_pose[BB*DD];               // 1 + pose_mod

// ---------------- helpers ---------------------------------------------------
__device__ __forceinline__ float ex2f(float x) {
    float y;
    asm("ex2.approx.f32 %0, %1;" : "=f"(y) : "f"(x));
    return y;
}
__device__ __forceinline__ uint32_t tf32cvt(float f) {
    uint32_t u;
    asm("cvt.rna.tf32.f32 %0, %1;" : "=r"(u) : "f"(f));
    return u;
}
__device__ __forceinline__ void mma_tf32(float& d0, float& d1, float& d2, float& d3,
                                         uint32_t a0, uint32_t a1, uint32_t a2, uint32_t a3,
                                         uint32_t b0, uint32_t b1) {
    asm("mma.sync.aligned.m16n8k8.row.col.f32.tf32.tf32.f32 "
        "{%0,%1,%2,%3}, {%4,%5,%6,%7}, {%8,%9}, {%0,%1,%2,%3};"
        : "+f"(d0), "+f"(d1), "+f"(d2), "+f"(d3)
        : "r"(a0), "r"(a1), "r"(a2), "r"(a3), "r"(b0), "r"(b1));
}

// ---------------- K1: patch-mean gather (batch-windowed for L2 locality) ----
// Blocks [0,512): each block handles 16 points per window, 2 windows of
// 8 batches (8192 points). Working set/window = 8 feature maps = 134MB ~ L2,
// so repeated random hits come from L2 instead of DRAM.
// Blocks [512,528): pose tail.
__global__ __launch_bounds__(256) void gather_kernel(
    const float* __restrict__ feat, const int* __restrict__ coords,
    const float* __restrict__ pe, const float* __restrict__ Wp,
    const float* __restrict__ bp)
{
    if (blockIdx.x >= 512) {            // ---- pose tail blocks ----
        int b = blockIdx.x - 512;
        int d = threadIdx.x;
        if (d < 64) {
            float s = bp[d];
            #pragma unroll 8
            for (int p = 0; p < 64; p++) s += pe[b*64 + p] * Wp[p*64 + d];
            g_pose[b*64 + d] = 1.0f + s;
        }
        return;
    }

    int t = threadIdx.x, w = t >> 5, lane = t & 31;
    int ch2 = lane >> 1, half = lane & 1;

    for (int win = 0; win < 2; win++) {
        int gp0 = win*8192 + blockIdx.x*16;

        #pragma unroll
        for (int ip = 0; ip < 2; ip++) {
            int gp = gp0 + w*2 + ip;
            int b  = gp >> 10;
            int y = __ldg(coords + gp*2 + 0);    // warp-uniform
            int x = __ldg(coords + gp*2 + 1);
            int s = x - 2;
            bool fast = (s >= 0) && (s <= 248);

            float part[4] = {0.f, 0.f, 0.f, 0.f};

            if (fast) {
                int a = s & ~3;
                int o = s - a;
                #pragma unroll
                for (int dy = 0; dy < 5; dy++) {
                    int yy = y + dy - 2;
                    int yc = min(max(yy, 0), HH-1);
                    float m = (yy == yc) ? 1.0f : 0.0f;
                    #pragma unroll
                    for (int cp = 0; cp < 4; cp++) {
                        int ch = cp*16 + ch2;
                        const float4* p = (const float4*)
                            (feat + ((size_t)(b*64 + ch) << 16) + yc*WW + a) + half;
                        float4 v = __ldg(p);
                        float ps;
                        if (half == 0) {
                            ps = v.w;
                            if (o < 3) ps += v.z;
                            if (o < 2) ps += v.y;
                            if (o < 1) ps += v.x;
                        } else {
                            ps = v.x;
                            if (o > 0) ps += v.y;
                            if (o > 1) ps += v.z;
                            if (o > 2) ps += v.w;
                        }
                        part[cp] = fmaf(m, ps, part[cp]);
                    }
                }
            } else {
                int base = x - 2 + half*4;
                int cnt  = half ? 1 : 4;
                for (int dy = 0; dy < 5; dy++) {
                    int yy = y + dy - 2;
                    if (yy < 0 || yy >= HH) continue;
                    #pragma unroll
                    for (int cp = 0; cp < 4; cp++) {
                        int ch = cp*16 + ch2;
                        const float* row = feat + ((size_t)(b*64 + ch) << 16) + yy*WW;
                        float ps = 0.f;
                        #pragma unroll
                        for (int i = 0; i < 4; i++) {
                            if (i < cnt) {
                                int xx = base + i;
                                if (xx >= 0 && xx < WW) ps += __ldg(row + xx);
                            }
                        }
                        part[cp] += ps;
                    }
                }
            }

            #pragma unroll
            for (int cp = 0; cp < 4; cp++) {
                float tot = part[cp] + __shfl_xor_sync(0xffffffff, part[cp], 1);
                if (half == 0)
                    g_PF[(size_t)gp*64 + cp*16 + ch2] = tot * 0.04f;
            }
        }
    }
}

// ---------------- K2: Q/K/V projection via tf32 mma -------------------------
#define ASTR 68
#define BSTR 136
extern __shared__ uint32_t PS[];
__global__ __launch_bounds__(256) void projection_mma_kernel(
    const float* __restrict__ desc,
    const float* __restrict__ Wq, const float* __restrict__ bq,
    const float* __restrict__ Wk, const float* __restrict__ bk,
    const float* __restrict__ Wv, const float* __restrict__ bv)
{
    uint32_t* As = PS;                  // 128 x ASTR
    uint32_t* Bs = PS + 128*ASTR;       // 64 x BSTR

    int t = threadIdx.x;
    int w = t >> 5, lane = t & 31, g = lane >> 2, t4 = lane & 3;
    int gp0 = blockIdx.x * 128;
    int b = gp0 >> 10, n0 = gp0 & 1023;

    // ======== pass 1: Q ========
    #pragma unroll
    for (int it = 0; it < 8; it++) {
        int i = t + 256*it;
        int r = i >> 4, c4 = (i & 15)*4;
        float4 v = __ldg((const float4*)(desc + (size_t)(gp0 + r)*64 + c4));
        *(uint4*)&As[r*ASTR + c4] =
            make_uint4(tf32cvt(v.x), tf32cvt(v.y), tf32cvt(v.z), tf32cvt(v.w));
    }
    #pragma unroll
    for (int it = 0; it < 4; it++) {
        int i = t + 256*it;
        int k = i >> 4, n4 = (i & 15)*4;
        float4 v = __ldg((const float4*)(Wq + k*64 + n4));
        *(uint4*)&Bs[k*BSTR + n4] =
            make_uint4(tf32cvt(v.x), tf32cvt(v.y), tf32cvt(v.z), tf32cvt(v.w));
    }
    __syncthreads();

    {
        uint32_t a[8][4];
        #pragma unroll
        for (int kc = 0; kc < 8; kc++) {
            int r0 = (w*16 + g)*ASTR + kc*8 + t4;
            a[kc][0] = As[r0];           a[kc][1] = As[r0 + 8*ASTR];
            a[kc][2] = As[r0 + 4];       a[kc][3] = As[r0 + 8*ASTR + 4];
        }
        #pragma unroll
        for (int nch = 0; nch < 8; nch++) {
            float d0=0.f, d1=0.f, d2=0.f, d3=0.f;
            #pragma unroll
            for (int kc = 0; kc < 8; kc++)
                mma_tf32(d0,d1,d2,d3, a[kc][0],a[kc][1],a[kc][2],a[kc][3],
                         Bs[(kc*8 + t4)*BSTR + nch*8 + g],
                         Bs[(kc*8 + t4 + 4)*BSTR + nch*8 + g]);
            int c = nch*8 + 2*t4;
            float bb0 = __ldg(bq + c), bb1 = __ldg(bq + c + 1);
            int h = c >> 4, j = c & 15;
            size_t idx = ((size_t)(b*NHH + h)*NN + n0 + w*16 + g)*HDD + j;
            *(float2*)&g_Q[idx]          = make_float2(d0 + bb0, d1 + bb1);
            *(float2*)&g_Q[idx + 8*HDD]  = make_float2(d2 + bb0, d3 + bb1);
        }
    }
    __syncthreads();

    // ======== pass 2: K | V ========
    #pragma unroll
    for (int it = 0; it < 8; it++) {
        int i = t + 256*it;
        int r = i >> 4, c4 = (i & 15)*4;
        float4 v = *(const float4*)(g_PF + (size_t)(gp0 + r)*64 + c4);
        *(uint4*)&As[r*ASTR + c4] =
            make_uint4(tf32cvt(v.x), tf32cvt(v.y), tf32cvt(v.z), tf32cvt(v.w));
    }
    #pragma unroll
    for (int it = 0; it < 4; it++) {
        int i = t + 256*it;
        int k = i >> 4, n4 = (i & 15)*4;
        float4 v = __ldg((const float4*)(Wk + k*64 + n4));
        *(uint4*)&Bs[k*BSTR + n4] =
            make_uint4(tf32cvt(v.x), tf32cvt(v.y), tf32cvt(v.z), tf32cvt(v.w));
    }
    #pragma unroll
    for (int it = 0; it < 4; it++) {
        int i = t + 256*it;
        int k = i >> 4, n4 = (i & 15)*4;
        float4 v = __ldg((const float4*)(Wv + k*64 + n4));
        *(uint4*)&Bs[k*BSTR + 64 + n4] =
            make_uint4(tf32cvt(v.x), tf32cvt(v.y), tf32cvt(v.z), tf32cvt(v.w));
    }
    __syncthreads();

    {
        uint32_t a[8][4];
        #pragma unroll
        for (int kc = 0; kc < 8; kc++) {
            int r0 = (w*16 + g)*ASTR + kc*8 + t4;
            a[kc][0] = As[r0];           a[kc][1] = As[r0 + 8*ASTR];
            a[kc][2] = As[r0 + 4];       a[kc][3] = As[r0 + 8*ASTR + 4];
        }
        #pragma unroll
        for (int nch = 0; nch < 16; nch++) {
            float d0=0.f, d1=0.f, d2=0.f, d3=0.f;
            #pragma unroll
            for (int kc = 0; kc < 8; kc++)
                mma_tf32(d0,d1,d2,d3, a[kc][0],a[kc][1],a[kc][2],a[kc][3],
                         Bs[(kc*8 + t4)*BSTR + nch*8 + g],
                         Bs[(kc*8 + t4 + 4)*BSTR + nch*8 + g]);
            int cfull = nch*8 + 2*t4;
            bool isK = (cfull < 64);
            int c = isK ? cfull : (cfull - 64);
            const float* bias = isK ? bk : bv;
            float* dst = isK ? g_K : g_V;
            float bb0 = __ldg(bias + c), bb1 = __ldg(bias + c + 1);
            int h = c >> 4, j = c & 15;
            size_t idx = ((size_t)(b*NHH + h)*NN + n0 + w*16 + g)*HDD + j;
            *(float2*)&dst[idx]         = make_float2(d0 + bb0, d1 + bb1);
            *(float2*)&dst[idx + 8*HDD] = make_float2(d2 + bb0, d3 + bb1);
        }
    }
}

// ---------------- K3: all-tf32 tensor-core attention ------------------------
#define KPAD 20
#define VPAD 24
__global__ __launch_bounds__(256) void attn_mma_kernel() {
    __shared__ uint32_t Ks[64*KPAD];
    __shared__ uint32_t Vs[64*VPAD];

    int t = threadIdx.x;
    int w = t >> 5, lane = t & 31, g = lane >> 2, t4 = lane & 3;
    int b = blockIdx.z, h = blockIdx.y;
    size_t bh = (size_t)(b*NHH + h) * NN * HDD;
    const float* Kg = g_K + bh;
    const float* Vg = g_V + bh;

    int qrow = blockIdx.x*128 + w*16;
    const float* Qp = g_Q + bh + (size_t)qrow*HDD;
    const float CSC = 0.25f * 1.4426950408889634f;

    uint32_t qa[2][4];
    #pragma unroll
    for (int c = 0; c < 2; c++) {
        qa[c][0] = tf32cvt(Qp[ g   *16 + c*8 + t4    ] * CSC);
        qa[c][1] = tf32cvt(Qp[(g+8)*16 + c*8 + t4    ] * CSC);
        qa[c][2] = tf32cvt(Qp[ g   *16 + c*8 + t4 + 4] * CSC);
        qa[c][3] = tf32cvt(Qp[(g+8)*16 + c*8 + t4 + 4] * CSC);
    }

    float o0[4] = {0,0,0,0};
    float o1[4] = {0,0,0,0};
    float rs0 = 0.0f, rs1 = 0.0f;

    int key = t >> 2, dc = t & 3;
    int vrow = (key & ~7) + 4*(key & 1) + ((key & 7) >> 1);

    float4 kreg = ((const float4*)Kg)[t];
    float4 vreg = ((const float4*)Vg)[t];

    for (int tile = 0; tile < 16; tile++) {
        __syncthreads();
        {
            uint32_t* kd = Ks + key*KPAD + dc*4;
            kd[0] = tf32cvt(kreg.x); kd[1] = tf32cvt(kreg.y);
            kd[2] = tf32cvt(kreg.z); kd[3] = tf32cvt(kreg.w);
            uint4 vv;
            vv.x = tf32cvt(vreg.x); vv.y = tf32cvt(vreg.y);
            vv.z = tf32cvt(vreg.z); vv.w = tf32cvt(vreg.w);
            *(uint4*)(Vs + vrow*VPAD + dc*4) = vv;
        }
        __syncthreads();
        if (tile < 15) {
            kreg = ((const float4*)(Kg + (size_t)(tile+1)*64*16))[t];
            vreg = ((const float4*)(Vg + (size_t)(tile+1)*64*16))[t];
        }

        #pragma unroll
        for (int j = 0; j < 8; j++) {
            float d0=0.f, d1=0.f, d2=0.f, d3=0.f;
            #pragma unroll
            for (int c = 0; c < 2; c++) {
                const uint32_t* kb = Ks + (j*8+g)*KPAD + c*8 + t4;
                mma_tf32(d0,d1,d2,d3, qa[c][0],qa[c][1],qa[c][2],qa[c][3],
                         kb[0], kb[4]);
            }
            float p0 = ex2f(d0), p1 = ex2f(d1), p2 = ex2f(d2), p3 = ex2f(d3);
            rs0 += p0 + p1;
            rs1 += p2 + p3;
            uint32_t a0 = __float_as_uint(p0), a1 = __float_as_uint(p2);
            uint32_t a2 = __float_as_uint(p1), a3 = __float_as_uint(p3);
            uint32_t b00 = Vs[(j*8 + t4    )*VPAD + g    ];
            uint32_t b01 = Vs[(j*8 + t4 + 4)*VPAD + g    ];
            uint32_t b10 = Vs[(j*8 + t4    )*VPAD + g + 8];
            uint32_t b11 = Vs[(j*8 + t4 + 4)*VPAD + g + 8];
            mma_tf32(o0[0],o0[1],o0[2],o0[3], a0,a1,a2,a3, b00,b01);
            mma_tf32(o1[0],o1[1],o1[2],o1[3], a0,a1,a2,a3, b10,b11);
        }
    }

    rs0 += __shfl_xor_sync(0xffffffff, rs0, 1);
    rs0 += __shfl_xor_sync(0xffffffff, rs0, 2);
    rs1 += __shfl_xor_sync(0xffffffff, rs1, 1);
    rs1 += __shfl_xor_sync(0xffffffff, rs1, 2);
    float inv0 = 1.0f / rs0;
    float inv1 = 1.0f / rs1;

    const float* ps = g_pose + b*64 + h*16;
    size_t r0 = ((size_t)b*NN + qrow + g    )*64 + h*16;
    size_t r1 = ((size_t)b*NN + qrow + g + 8)*64 + h*16;
    #pragma unroll
    for (int nd = 0; nd < 2; nd++) {
        const float* o = nd ? o1 : o0;
        int cc = nd*8 + 2*t4;
        float p0 = ps[cc], p1 = ps[cc+1];
        *(float2*)&g_att[r0 + cc] = make_float2(o[0]*inv0*p0, o[1]*inv0*p1);
        *(float2*)&g_att[r1 + cc] = make_float2(o[2]*inv1*p0, o[3]*inv1*p1);
    }
}

// ---------------- K4: out = g_att @ Wo + bo via tf32 mma --------------------
#define OBSTR 72
extern __shared__ uint32_t OS[];
__global__ __launch_bounds__(256) void outproj_mma_kernel(
    const float* __restrict__ Wo, const float* __restrict__ bo,
    float* __restrict__ out)
{
    uint32_t* As = OS;
    uint32_t* Bs = OS + 128*ASTR;

    int t = threadIdx.x;
    int w = t >> 5, lane = t & 31, g = lane >> 2, t4 = lane & 3;
    size_t gp0 = (size_t)blockIdx.x * 128;

    #pragma unroll
    for (int it = 0; it < 8; it++) {
        int i = t + 256*it;
        int r = i >> 4, c4 = (i & 15)*4;
        float4 v = *(const float4*)(g_att + (gp0 + r)*64 + c4);
        *(uint4*)&As[r*ASTR + c4] =
            make_uint4(tf32cvt(v.x), tf32cvt(v.y), tf32cvt(v.z), tf32cvt(v.w));
    }
    #pragma unroll
    for (int it = 0; it < 4; it++) {
        int i = t + 256*it;
        int k = i >> 4, n4 = (i & 15)*4;
        float4 v = __ldg((const float4*)(Wo + k*64 + n4));
        *(uint4*)&Bs[k*OBSTR + n4] =
            make_uint4(tf32cvt(v.x), tf32cvt(v.y), tf32cvt(v.z), tf32cvt(v.w));
    }
    __syncthreads();

    uint32_t a[8][4];
    #pragma unroll
    for (int kc = 0; kc < 8; kc++) {
        int r0 = (w*16 + g)*ASTR + kc*8 + t4;
        a[kc][0] = As[r0];           a[kc][1] = As[r0 + 8*ASTR];
        a[kc][2] = As[r0 + 4];       a[kc][3] = As[r0 + 8*ASTR + 4];
    }
    #pragma unroll
    for (int nch = 0; nch < 8; nch++) {
        float d0=0.f, d1=0.f, d2=0.f, d3=0.f;
        #pragma unroll
        for (int kc = 0; kc < 8; kc++)
            mma_tf32(d0,d1,d2,d3, a[kc][0],a[kc][1],a[kc][2],a[kc][3],
                     Bs[(kc*8 + t4)*OBSTR + nch*8 + g],
                     Bs[(kc*8 + t4 + 4)*OBSTR + nch*8 + g]);
        int c = nch*8 + 2*t4;
        float bb0 = __ldg(bo + c), bb1 = __ldg(bo + c + 1);
        size_t r0i = (gp0 + w*16 + g)*64 + c;
        *(float2*)&out[r0i]          = make_float2(d0 + bb0, d1 + bb1);
        *(float2*)&out[r0i + 8*64]   = make_float2(d2 + bb0, d3 + bb1);
    }
}

// ---------------- launch ----------------------------------------------------
extern "C" void kernel_launch(void* const* d_in, const int* in_sizes, int n_in,
                              void* d_out, int out_size) {
    const float* desc   = (const float*)d_in[0];
    const float* feat   = (const float*)d_in[1];
    const int*   coords = (const int*)  d_in[2];
    const float* pose   = (const float*)d_in[3];
    const float* Wq = (const float*)d_in[4];  const float* bq = (const float*)d_in[5];
    const float* Wk = (const float*)d_in[6];  const float* bk = (const float*)d_in[7];
    const float* Wv = (const float*)d_in[8];  const float* bv = (const float*)d_in[9];
    const float* Wp = (const float*)d_in[10]; const float* bp = (const float*)d_in[11];
    const float* Wo = (const float*)d_in[12]; const float* bo = (const float*)d_in[13];
    float* out = (float*)d_out;

    int psm = (128*ASTR + 64*BSTR) * 4;     // 69,632 B
    cudaFuncSetAttribute(projection_mma_kernel,
                         cudaFuncAttributeMaxDynamicSharedMemorySize, psm);
    int osm = (128*ASTR + 64*OBSTR) * 4;    // 53,248 B
    cudaFuncSetAttribute(outproj_mma_kernel,
                         cudaFuncAttributeMaxDynamicSharedMemorySize, osm);

    gather_kernel<<<512 + BB, 256>>>(feat, coords, pose, Wp, bp);
    projection_mma_kernel<<<128, 256, psm>>>(desc, Wq, bq, Wk, bk, Wv, bv);
    attn_mma_kernel<<<dim3(8, NHH, BB), 256>>>();
    outproj_mma_kernel<<<128, 256, osm>>>(Wo, bo, out);
}

// round 15
// speedup vs baseline: 2.1019x; 1.0731x over previous
#include <cuda_runtime.h>
#include <cstdint>

#define BB 16
#define NN 1024
#define DD 64
#define NHH 4
#define HDD 16
#define HH 256
#define WW 256

// ---------------- scratch (device globals: no runtime allocation) ----------
__device__ float g_Q[BB*NHH*NN*HDD];          // (b,h,n,j) 4MB
__device__ float g_K[BB*NHH*NN*HDD];          // 4MB
__device__ float g_V[BB*NHH*NN*HDD];          // 4MB
__device__ float g_PF[BB*NN*DD];              // patch means 4MB
__device__ float g_att[BB*NN*DD];             // pose-scaled attention out 4MB
__device__ float g_pose[BB*DD];               // 1 + pose_mod

// ---------------- helpers ---------------------------------------------------
__device__ __forceinline__ float ex2f(float x) {
    float y;
    asm("ex2.approx.f32 %0, %1;" : "=f"(y) : "f"(x));
    return y;
}
__device__ __forceinline__ uint32_t tf32cvt(float f) {
    uint32_t u;
    asm("cvt.rna.tf32.f32 %0, %1;" : "=r"(u) : "f"(f));
    return u;
}
__device__ __forceinline__ void mma_tf32(float& d0, float& d1, float& d2, float& d3,
                                         uint32_t a0, uint32_t a1, uint32_t a2, uint32_t a3,
                                         uint32_t b0, uint32_t b1) {
    asm("mma.sync.aligned.m16n8k8.row.col.f32.tf32.tf32.f32 "
        "{%0,%1,%2,%3}, {%4,%5,%6,%7}, {%8,%9}, {%0,%1,%2,%3};"
        : "+f"(d0), "+f"(d1), "+f"(d2), "+f"(d3)
        : "r"(a0), "r"(a1), "r"(a2), "r"(a3), "r"(b0), "r"(b1));
}

// ---------------- K1: patch-mean gather (4 windows of 4 batches) ------------
// Blocks [0,512): per window, 8 points/block (warp = 1 point). Working set
// per window = 4 feature maps = 67MB << L2, so repeat touches hit L2.
// Blocks [512,528): pose tail.
__global__ __launch_bounds__(256) void gather_kernel(
    const float* __restrict__ feat, const int* __restrict__ coords,
    const float* __restrict__ pe, const float* __restrict__ Wp,
    const float* __restrict__ bp)
{
    if (blockIdx.x >= 512) {            // ---- pose tail blocks ----
        int b = blockIdx.x - 512;
        int d = threadIdx.x;
        if (d < 64) {
            float s = bp[d];
            #pragma unroll 8
            for (int p = 0; p < 64; p++) s += pe[b*64 + p] * Wp[p*64 + d];
            g_pose[b*64 + d] = 1.0f + s;
        }
        return;
    }

    int t = threadIdx.x, w = t >> 5, lane = t & 31;
    int ch2 = lane >> 1, half = lane & 1;

    #pragma unroll 1
    for (int win = 0; win < 4; win++) {
        int gp = win*4096 + blockIdx.x*8 + w;
        int b  = gp >> 10;
        int y = __ldg(coords + gp*2 + 0);    // warp-uniform
        int x = __ldg(coords + gp*2 + 1);
        int s = x - 2;
        bool fast = (s >= 0) && (s <= 248);

        float part[4] = {0.f, 0.f, 0.f, 0.f};

        if (fast) {
            int a = s & ~3;
            int o = s - a;
            #pragma unroll
            for (int dy = 0; dy < 5; dy++) {
                int yy = y + dy - 2;
                int yc = min(max(yy, 0), HH-1);
                float m = (yy == yc) ? 1.0f : 0.0f;
                #pragma unroll
                for (int cp = 0; cp < 4; cp++) {
                    int ch = cp*16 + ch2;
                    const float4* p = (const float4*)
                        (feat + ((size_t)(b*64 + ch) << 16) + yc*WW + a) + half;
                    float4 v = __ldg(p);
                    float ps;
                    if (half == 0) {
                        ps = v.w;
                        if (o < 3) ps += v.z;
                        if (o < 2) ps += v.y;
                        if (o < 1) ps += v.x;
                    } else {
                        ps = v.x;
                        if (o > 0) ps += v.y;
                        if (o > 1) ps += v.z;
                        if (o > 2) ps += v.w;
                    }
                    part[cp] = fmaf(m, ps, part[cp]);
                }
            }
        } else {
            int base = x - 2 + half*4;
            int cnt  = half ? 1 : 4;
            for (int dy = 0; dy < 5; dy++) {
                int yy = y + dy - 2;
                if (yy < 0 || yy >= HH) continue;
                #pragma unroll
                for (int cp = 0; cp < 4; cp++) {
                    int ch = cp*16 + ch2;
                    const float* row = feat + ((size_t)(b*64 + ch) << 16) + yy*WW;
                    float ps = 0.f;
                    #pragma unroll
                    for (int i = 0; i < 4; i++) {
                        if (i < cnt) {
                            int xx = base + i;
                            if (xx >= 0 && xx < WW) ps += __ldg(row + xx);
                        }
                    }
                    part[cp] += ps;
                }
            }
        }

        #pragma unroll
        for (int cp = 0; cp < 4; cp++) {
            float tot = part[cp] + __shfl_xor_sync(0xffffffff, part[cp], 1);
            if (half == 0)
                g_PF[(size_t)gp*64 + cp*16 + ch2] = tot * 0.04f;
        }
    }
}

// ---------------- K2: Q/K/V projection via tf32 mma -------------------------
#define ASTR 68
#define BSTR 136
extern __shared__ uint32_t PS[];
__global__ __launch_bounds__(256) void projection_mma_kernel(
    const float* __restrict__ desc,
    const float* __restrict__ Wq, const float* __restrict__ bq,
    const float* __restrict__ Wk, const float* __restrict__ bk,
    const float* __restrict__ Wv, const float* __restrict__ bv)
{
    uint32_t* As = PS;                  // 128 x ASTR
    uint32_t* Bs = PS + 128*ASTR;       // 64 x BSTR

    int t = threadIdx.x;
    int w = t >> 5, lane = t & 31, g = lane >> 2, t4 = lane & 3;
    int gp0 = blockIdx.x * 128;
    int b = gp0 >> 10, n0 = gp0 & 1023;

    // ======== pass 1: Q ========
    #pragma unroll
    for (int it = 0; it < 8; it++) {
        int i = t + 256*it;
        int r = i >> 4, c4 = (i & 15)*4;
        float4 v = __ldg((const float4*)(desc + (size_t)(gp0 + r)*64 + c4));
        *(uint4*)&As[r*ASTR + c4] =
            make_uint4(tf32cvt(v.x), tf32cvt(v.y), tf32cvt(v.z), tf32cvt(v.w));
    }
    #pragma unroll
    for (int it = 0; it < 4; it++) {
        int i = t + 256*it;
        int k = i >> 4, n4 = (i & 15)*4;
        float4 v = __ldg((const float4*)(Wq + k*64 + n4));
        *(uint4*)&Bs[k*BSTR + n4] =
            make_uint4(tf32cvt(v.x), tf32cvt(v.y), tf32cvt(v.z), tf32cvt(v.w));
    }
    __syncthreads();

    {
        uint32_t a[8][4];
        #pragma unroll
        for (int kc = 0; kc < 8; kc++) {
            int r0 = (w*16 + g)*ASTR + kc*8 + t4;
            a[kc][0] = As[r0];           a[kc][1] = As[r0 + 8*ASTR];
            a[kc][2] = As[r0 + 4];       a[kc][3] = As[r0 + 8*ASTR + 4];
        }
        #pragma unroll
        for (int nch = 0; nch < 8; nch++) {
            float d0=0.f, d1=0.f, d2=0.f, d3=0.f;
            #pragma unroll
            for (int kc = 0; kc < 8; kc++)
                mma_tf32(d0,d1,d2,d3, a[kc][0],a[kc][1],a[kc][2],a[kc][3],
                         Bs[(kc*8 + t4)*BSTR + nch*8 + g],
                         Bs[(kc*8 + t4 + 4)*BSTR + nch*8 + g]);
            int c = nch*8 + 2*t4;
            float bb0 = __ldg(bq + c), bb1 = __ldg(bq + c + 1);
            int h = c >> 4, j = c & 15;
            size_t idx = ((size_t)(b*NHH + h)*NN + n0 + w*16 + g)*HDD + j;
            *(float2*)&g_Q[idx]          = make_float2(d0 + bb0, d1 + bb1);
            *(float2*)&g_Q[idx + 8*HDD]  = make_float2(d2 + bb0, d3 + bb1);
        }
    }
    __syncthreads();

    // ======== pass 2: K | V ========
    #pragma unroll
    for (int it = 0; it < 8; it++) {
        int i = t + 256*it;
        int r = i >> 4, c4 = (i & 15)*4;
        float4 v = *(const float4*)(g_PF + (size_t)(gp0 + r)*64 + c4);
        *(uint4*)&As[r*ASTR + c4] =
            make_uint4(tf32cvt(v.x), tf32cvt(v.y), tf32cvt(v.z), tf32cvt(v.w));
    }
    #pragma unroll
    for (int it = 0; it < 4; it++) {
        int i = t + 256*it;
        int k = i >> 4, n4 = (i & 15)*4;
        float4 v = __ldg((const float4*)(Wk + k*64 + n4));
        *(uint4*)&Bs[k*BSTR + n4] =
            make_uint4(tf32cvt(v.x), tf32cvt(v.y), tf32cvt(v.z), tf32cvt(v.w));
    }
    #pragma unroll
    for (int it = 0; it < 4; it++) {
        int i = t + 256*it;
        int k = i >> 4, n4 = (i & 15)*4;
        float4 v = __ldg((const float4*)(Wv + k*64 + n4));
        *(uint4*)&Bs[k*BSTR + 64 + n4] =
            make_uint4(tf32cvt(v.x), tf32cvt(v.y), tf32cvt(v.z), tf32cvt(v.w));
    }
    __syncthreads();

    {
        uint32_t a[8][4];
        #pragma unroll
        for (int kc = 0; kc < 8; kc++) {
            int r0 = (w*16 + g)*ASTR + kc*8 + t4;
            a[kc][0] = As[r0];           a[kc][1] = As[r0 + 8*ASTR];
            a[kc][2] = As[r0 + 4];       a[kc][3] = As[r0 + 8*ASTR + 4];
        }
        #pragma unroll
        for (int nch = 0; nch < 16; nch++) {
            float d0=0.f, d1=0.f, d2=0.f, d3=0.f;
            #pragma unroll
            for (int kc = 0; kc < 8; kc++)
                mma_tf32(d0,d1,d2,d3, a[kc][0],a[kc][1],a[kc][2],a[kc][3],
                         Bs[(kc*8 + t4)*BSTR + nch*8 + g],
                         Bs[(kc*8 + t4 + 4)*BSTR + nch*8 + g]);
            int cfull = nch*8 + 2*t4;
            bool isK = (cfull < 64);
            int c = isK ? cfull : (cfull - 64);
            const float* bias = isK ? bk : bv;
            float* dst = isK ? g_K : g_V;
            float bb0 = __ldg(bias + c), bb1 = __ldg(bias + c + 1);
            int h = c >> 4, j = c & 15;
            size_t idx = ((size_t)(b*NHH + h)*NN + n0 + w*16 + g)*HDD + j;
            *(float2*)&dst[idx]         = make_float2(d0 + bb0, d1 + bb1);
            *(float2*)&dst[idx + 8*HDD] = make_float2(d2 + bb0, d3 + bb1);
        }
    }
}

// ---------------- K3: all-tf32 attention, 512 thr, double-buffered ----------
// grid (4, NH, B) = 256 blocks, 16 warps/block (256 q rows). K/V tiles
// ping-pong in smem: ONE __syncthreads per tile; next tile's global loads
// issued before compute.
#define KPAD 20
#define VPAD 24
__global__ __launch_bounds__(512) void attn_mma_kernel() {
    __shared__ uint32_t Ks[2][64*KPAD];
    __shared__ uint32_t Vs[2][64*VPAD];

    int t = threadIdx.x;
    int w = t >> 5, lane = t & 31, g = lane >> 2, t4 = lane & 3;
    int b = blockIdx.z, h = blockIdx.y;
    size_t bh = (size_t)(b*NHH + h) * NN * HDD;
    const float* Kg = g_K + bh;
    const float* Vg = g_V + bh;

    int qrow = blockIdx.x*256 + w*16;
    const float* Qp = g_Q + bh + (size_t)qrow*HDD;
    const float CSC = 0.25f * 1.4426950408889634f;

    uint32_t qa[2][4];
    #pragma unroll
    for (int c = 0; c < 2; c++) {
        qa[c][0] = tf32cvt(Qp[ g   *16 + c*8 + t4    ] * CSC);
        qa[c][1] = tf32cvt(Qp[(g+8)*16 + c*8 + t4    ] * CSC);
        qa[c][2] = tf32cvt(Qp[ g   *16 + c*8 + t4 + 4] * CSC);
        qa[c][3] = tf32cvt(Qp[(g+8)*16 + c*8 + t4 + 4] * CSC);
    }

    float o0[4] = {0,0,0,0};
    float o1[4] = {0,0,0,0};
    float rs0 = 0.0f, rs1 = 0.0f;

    // loader roles: threads [0,256) load K, [256,512) load V
    bool isK = (t < 256);
    int lt = isK ? t : (t - 256);
    int key = lt >> 2, dc = lt & 3;
    int vrow = (key & ~7) + 4*(key & 1) + ((key & 7) >> 1);

    // preload + store tile 0
    float4 reg = isK ? ((const float4*)Kg)[lt] : ((const float4*)Vg)[lt];
    {
        uint4 vv;
        vv.x = tf32cvt(reg.x); vv.y = tf32cvt(reg.y);
        vv.z = tf32cvt(reg.z); vv.w = tf32cvt(reg.w);
        if (isK) *(uint4*)(Ks[0] + key*KPAD + dc*4) = vv;
        else     *(uint4*)(Vs[0] + vrow*VPAD + dc*4) = vv;
    }
    __syncthreads();

    for (int tile = 0; tile < 16; tile++) {
        int buf = tile & 1;
        if (tile < 15) {                    // overlap next-tile global load
            const float* src = isK ? (Kg + (size_t)(tile+1)*64*16)
                                   : (Vg + (size_t)(tile+1)*64*16);
            reg = ((const float4*)src)[lt];
        }

        const uint32_t* ks = Ks[buf];
        const uint32_t* vs = Vs[buf];
        #pragma unroll
        for (int j = 0; j < 8; j++) {
            float d0=0.f, d1=0.f, d2=0.f, d3=0.f;
            #pragma unroll
            for (int c = 0; c < 2; c++) {
                const uint32_t* kb = ks + (j*8+g)*KPAD + c*8 + t4;
                mma_tf32(d0,d1,d2,d3, qa[c][0],qa[c][1],qa[c][2],qa[c][3],
                         kb[0], kb[4]);
            }
            float p0 = ex2f(d0), p1 = ex2f(d1), p2 = ex2f(d2), p3 = ex2f(d3);
            rs0 += p0 + p1;
            rs1 += p2 + p3;
            uint32_t a0 = __float_as_uint(p0), a1 = __float_as_uint(p2);
            uint32_t a2 = __float_as_uint(p1), a3 = __float_as_uint(p3);
            uint32_t b00 = vs[(j*8 + t4    )*VPAD + g    ];
            uint32_t b01 = vs[(j*8 + t4 + 4)*VPAD + g    ];
            uint32_t b10 = vs[(j*8 + t4    )*VPAD + g + 8];
            uint32_t b11 = vs[(j*8 + t4 + 4)*VPAD + g + 8];
            mma_tf32(o0[0],o0[1],o0[2],o0[3], a0,a1,a2,a3, b00,b01);
            mma_tf32(o1[0],o1[1],o1[2],o1[3], a0,a1,a2,a3, b10,b11);
        }

        if (tile < 15) {                    // store next tile, single barrier
            int nbuf = (tile + 1) & 1;
            uint4 vv;
            vv.x = tf32cvt(reg.x); vv.y = tf32cvt(reg.y);
            vv.z = tf32cvt(reg.z); vv.w = tf32cvt(reg.w);
            if (isK) *(uint4*)(Ks[nbuf] + key*KPAD + dc*4) = vv;
            else     *(uint4*)(Vs[nbuf] + vrow*VPAD + dc*4) = vv;
            __syncthreads();
        }
    }

    rs0 += __shfl_xor_sync(0xffffffff, rs0, 1);
    rs0 += __shfl_xor_sync(0xffffffff, rs0, 2);
    rs1 += __shfl_xor_sync(0xffffffff, rs1, 1);
    rs1 += __shfl_xor_sync(0xffffffff, rs1, 2);
    float inv0 = 1.0f / rs0;
    float inv1 = 1.0f / rs1;

    const float* ps = g_pose + b*64 + h*16;
    size_t r0 = ((size_t)b*NN + qrow + g    )*64 + h*16;
    size_t r1 = ((size_t)b*NN + qrow + g + 8)*64 + h*16;
    #pragma unroll
    for (int nd = 0; nd < 2; nd++) {
        const float* o = nd ? o1 : o0;
        int cc = nd*8 + 2*t4;
        float p0 = ps[cc], p1 = ps[cc+1];
        *(float2*)&g_att[r0 + cc] = make_float2(o[0]*inv0*p0, o[1]*inv0*p1);
        *(float2*)&g_att[r1 + cc] = make_float2(o[2]*inv1*p0, o[3]*inv1*p1);
    }
}

// ---------------- K4: out = g_att @ Wo + bo via tf32 mma --------------------
#define OBSTR 72
extern __shared__ uint32_t OS[];
__global__ __launch_bounds__(256) void outproj_mma_kernel(
    const float* __restrict__ Wo, const float* __restrict__ bo,
    float* __restrict__ out)
{
    uint32_t* As = OS;
    uint32_t* Bs = OS + 128*ASTR;

    int t = threadIdx.x;
    int w = t >> 5, lane = t & 31, g = lane >> 2, t4 = lane & 3;
    size_t gp0 = (size_t)blockIdx.x * 128;

    #pragma unroll
    for (int it = 0; it < 8; it++) {
        int i = t + 256*it;
        int r = i >> 4, c4 = (i & 15)*4;
        float4 v = *(const float4*)(g_att + (gp0 + r)*64 + c4);
        *(uint4*)&As[r*ASTR + c4] =
            make_uint4(tf32cvt(v.x), tf32cvt(v.y), tf32cvt(v.z), tf32cvt(v.w));
    }
    #pragma unroll
    for (int it = 0; it < 4; it++) {
        int i = t + 256*it;
        int k = i >> 4, n4 = (i & 15)*4;
        float4 v = __ldg((const float4*)(Wo + k*64 + n4));
        *(uint4*)&Bs[k*OBSTR + n4] =
            make_uint4(tf32cvt(v.x), tf32cvt(v.y), tf32cvt(v.z), tf32cvt(v.w));
    }
    __syncthreads();

    uint32_t a[8][4];
    #pragma unroll
    for (int kc = 0; kc < 8; kc++) {
        int r0 = (w*16 + g)*ASTR + kc*8 + t4;
        a[kc][0] = As[r0];           a[kc][1] = As[r0 + 8*ASTR];
        a[kc][2] = As[r0 + 4];       a[kc][3] = As[r0 + 8*ASTR + 4];
    }
    #pragma unroll
    for (int nch = 0; nch < 8; nch++) {
        float d0=0.f, d1=0.f, d2=0.f, d3=0.f;
        #pragma unroll
        for (int kc = 0; kc < 8; kc++)
            mma_tf32(d0,d1,d2,d3, a[kc][0],a[kc][1],a[kc][2],a[kc][3],
                     Bs[(kc*8 + t4)*OBSTR + nch*8 + g],
                     Bs[(kc*8 + t4 + 4)*OBSTR + nch*8 + g]);
        int c = nch*8 + 2*t4;
        float bb0 = __ldg(bo + c), bb1 = __ldg(bo + c + 1);
        size_t r0i = (gp0 + w*16 + g)*64 + c;
        *(float2*)&out[r0i]          = make_float2(d0 + bb0, d1 + bb1);
        *(float2*)&out[r0i + 8*64]   = make_float2(d2 + bb0, d3 + bb1);
    }
}

// ---------------- launch ----------------------------------------------------
extern "C" void kernel_launch(void* const* d_in, const int* in_sizes, int n_in,
                              void* d_out, int out_size) {
    const float* desc   = (const float*)d_in[0];
    const float* feat   = (const float*)d_in[1];
    const int*   coords = (const int*)  d_in[2];
    const float* pose   = (const float*)d_in[3];
    const float* Wq = (const float*)d_in[4];  const float* bq = (const float*)d_in[5];
    const float* Wk = (const float*)d_in[6];  const float* bk = (const float*)d_in[7];
    const float* Wv = (const float*)d_in[8];  const float* bv = (const float*)d_in[9];
    const float* Wp = (const float*)d_in[10]; const float* bp = (const float*)d_in[11];
    const float* Wo = (const float*)d_in[12]; const float* bo = (const float*)d_in[13];
    float* out = (float*)d_out;

    int psm = (128*ASTR + 64*BSTR) * 4;     // 69,632 B
    cudaFuncSetAttribute(projection_mma_kernel,
                         cudaFuncAttributeMaxDynamicSharedMemorySize, psm);
    int osm = (128*ASTR + 64*OBSTR) * 4;    // 53,248 B
    cudaFuncSetAttribute(outproj_mma_kernel,
                         cudaFuncAttributeMaxDynamicSharedMemorySize, osm);

    gather_kernel<<<512 + BB, 256>>>(feat, coords, pose, Wp, bp);
    projection_mma_kernel<<<128, 256, psm>>>(desc, Wq, bq, Wk, bk, Wv, bv);
    attn_mma_kernel<<<dim3(4, NHH, BB), 512>>>();
    outproj_mma_kernel<<<128, 256, osm>>>(Wo, bo, out);
}